// round 1
// baseline (speedup 1.0000x reference)
#include <cuda_runtime.h>

#define IMG_W 1024
#define IMG_H 1024

// Zero the output image (harness poisons d_out with 0xAA).
__global__ void zero_img_kernel(float4* __restrict__ img, int n4) {
    int i = blockIdx.x * blockDim.x + threadIdx.x;
    if (i < n4) img[i] = make_float4(0.f, 0.f, 0.f, 0.f);
}

// One thread per point. Separable Gaussian: weight(o) = exp(-50*(frac-o)^2).
// Normalizer uses all 5 taps per dim (matches reference mass to ~1e-6);
// splat only the {0,1}x{0,1} quad — all other taps are <= e^-50 (~2e-22)
// of the point's mass, 19 orders of magnitude below the 1e-3 tolerance.
__global__ __launch_bounds__(256)
void splat_kernel(const float* __restrict__ xs,
                  const float* __restrict__ ys,
                  const float* __restrict__ vs,
                  float* __restrict__ img, int n)
{
    int i = blockIdx.x * blockDim.x + threadIdx.x;
    if (i >= n) return;

    // x_pix = (x - X0)/DX = (x + 1) * 512  (exact in fp32)
    float xp = (xs[i] + 1.0f) * 512.0f;
    float yp = (ys[i] + 1.0f) * 512.0f;
    float val = vs[i];

    float fxb = floorf(xp), fyb = floorf(yp);
    int   xb  = (int)fxb,   yb  = (int)fyb;
    float fx  = xp - fxb,   fy  = yp - fyb;   // in [0,1)

    // 5 taps per dimension for the normalizing sums; keep taps o=0 and o=1.
    float sx = 0.f, sy = 0.f;
    float wx0 = 0.f, wx1 = 0.f, wy0 = 0.f, wy1 = 0.f;
    #pragma unroll
    for (int o = -2; o <= 2; ++o) {
        float dx = fx - (float)o;
        float dy = fy - (float)o;
        float ex = __expf(-50.0f * dx * dx);
        float ey = __expf(-50.0f * dy * dy);
        sx += ex;  sy += ey;
        if (o == 0) { wx0 = ex; wy0 = ey; }
        if (o == 1) { wx1 = ex; wy1 = ey; }
    }
    float inv = 1.0f / (sx * sy);

    float w00 = wx0 * wy0 * inv;
    float w10 = wx1 * wy0 * inv;
    float w01 = wx0 * wy1 * inv;
    float w11 = wx1 * wy1 * inv;

    const float T = 1e-12f;  // normalized-weight gate; skipped mass <= 1e-12/point
    bool x0 = (xb     >= 0) & (xb     < IMG_W);
    bool x1 = (xb + 1 >= 0) & (xb + 1 < IMG_W);
    bool y0 = (yb     >= 0) & (yb     < IMG_H);
    bool y1 = (yb + 1 >= 0) & (yb + 1 < IMG_H);

    long long base = (long long)yb * IMG_W + xb;
    if (w00 > T && x0 && y0) atomicAdd(img + base,             w00 * val);
    if (w10 > T && x1 && y0) atomicAdd(img + base + 1,         w10 * val);
    if (w01 > T && x0 && y1) atomicAdd(img + base + IMG_W,     w01 * val);
    if (w11 > T && x1 && y1) atomicAdd(img + base + IMG_W + 1, w11 * val);
}

extern "C" void kernel_launch(void* const* d_in, const int* in_sizes, int n_in,
                              void* d_out, int out_size) {
    const float* xs = (const float*)d_in[0];
    const float* ys = (const float*)d_in[1];
    const float* vs = (const float*)d_in[2];
    float* img = (float*)d_out;
    int n = in_sizes[0];

    int n4 = out_size / 4;
    zero_img_kernel<<<(n4 + 255) / 256, 256>>>((float4*)img, n4);
    splat_kernel<<<(n + 255) / 256, 256>>>(xs, ys, vs, img, n);
}

// round 2
// speedup vs baseline: 1.4641x; 1.4641x over previous
#include <cuda_runtime.h>

#define IMG_W 1024
#define IMG_H 1024

// Zero the output image (harness poisons d_out with 0xAA).
__global__ void zero_img_kernel(float4* __restrict__ img, int n4) {
    int i = blockIdx.x * blockDim.x + threadIdx.x;
    if (i < n4) img[i] = make_float4(0.f, 0.f, 0.f, 0.f);
}

// One thread per point. Separable Gaussian, sigma=0.1 => exponent -50*d^2.
// Normalizer: of the 5 taps per dim, only offsets {0,1} are representable
// (|d|>=1 gives raw weight <= e^-50 ~ 2e-22 vs dominant >= e^-12.5 ~ 3.7e-6,
// a <=5e-17 relative contribution — below fp32 ulp). So 2 exps per dim.
// Splat gate T=2e-4 on the normalized weight: dropped mass per tap <= 2e-4,
// ~1% of points have a tap near threshold => rel_err contribution ~5e-5,
// well under the 1e-3 tolerance.
__global__ __launch_bounds__(256)
void splat_kernel(const float* __restrict__ xs,
                  const float* __restrict__ ys,
                  const float* __restrict__ vs,
                  float* __restrict__ img, int n)
{
    int i = blockIdx.x * blockDim.x + threadIdx.x;
    if (i >= n) return;

    // x_pix = (x + 1) * 512 (exact in fp32)
    float xp = (xs[i] + 1.0f) * 512.0f;
    float yp = (ys[i] + 1.0f) * 512.0f;
    float val = vs[i];

    float fxb = floorf(xp), fyb = floorf(yp);
    int   xb  = (int)fxb,   yb  = (int)fyb;
    float fx  = xp - fxb,   fy  = yp - fyb;   // in [0,1)

    float gx = 1.0f - fx, gy = 1.0f - fy;
    float ex0 = __expf(-50.0f * fx * fx);
    float ex1 = __expf(-50.0f * gx * gx);
    float ey0 = __expf(-50.0f * fy * fy);
    float ey1 = __expf(-50.0f * gy * gy);

    float inv = 1.0f / ((ex0 + ex1) * (ey0 + ey1));
    float vi  = val * inv;

    float w00 = ex0 * ey0;
    float w10 = ex1 * ey0;
    float w01 = ex0 * ey1;
    float w11 = ex1 * ey1;

    const float T = 2e-4f;           // gate on normalized weight
    float t = T / inv;               // compare in un-normalized space (1 mul)

    bool x1ok = (xb + 1 < IMG_W);
    bool y1ok = (yb + 1 < IMG_H);

    float* p = img + yb * IMG_W + xb;
    if (w00 > t)                 atomicAdd(p,             w00 * vi);
    if (w10 > t && x1ok)         atomicAdd(p + 1,         w10 * vi);
    if (w01 > t && y1ok)         atomicAdd(p + IMG_W,     w01 * vi);
    if (w11 > t && x1ok && y1ok) atomicAdd(p + IMG_W + 1, w11 * vi);
}

extern "C" void kernel_launch(void* const* d_in, const int* in_sizes, int n_in,
                              void* d_out, int out_size) {
    const float* xs = (const float*)d_in[0];
    const float* ys = (const float*)d_in[1];
    const float* vs = (const float*)d_in[2];
    float* img = (float*)d_out;
    int n = in_sizes[0];

    int n4 = out_size / 4;
    zero_img_kernel<<<(n4 + 255) / 256, 256>>>((float4*)img, n4);
    splat_kernel<<<(n + 255) / 256, 256>>>(xs, ys, vs, img, n);
}